// round 2
// baseline (speedup 1.0000x reference)
#include <cuda_runtime.h>
#include <cuda_bf16.h>
#include <cstdint>

// ---------------------------------------------------------------------------
// Persistent 2-layer tanh RNN.  B=64, T=512, D=H0=H1=1024, K=2048.
// 128 CTAs: blockIdx 0..63 = layer0 (cols 16*cta), 64..127 = layer1.
// Layer-pipelined phases p=0..512:
//   layer0 at phase p computes h0[t=p]      (reads h0[p-1], x[p])
//   layer1 at phase p computes h1[t=p-1]    (reads h1[p-2], h0[p-1])
// Grid barrier (epoch-based, monotonic counter) between phases.
// Weights in SMEM fp32; A=[h;inp] staged in SMEM via double-buffered
// cp.async.cg (L2-only => coherent with st.global.cg hidden-state writes).
// Math: packed fp32x2 FMA (fma.rn.f32x2) over column pairs.
// ---------------------------------------------------------------------------

#define BZ      64
#define TT      512
#define DD      1024
#define HH      1024
#define KDIM    2048
#define NCOL    16
#define THREADS 128
#define NCTA    128
#define CHUNK   128
#define NCHUNK  (KDIM / CHUNK)      // 16
#define KP4     33                  // float4 stride per batch row in A smem (pad)
#define A_F4    (BZ * KP4)          // 2112 float4 per A buffer
#define W_F4    (KDIM * 4)          // 8192 float4 for 2048x16 weights
#define SMEM_BYTES ((W_F4 + 2 * A_F4) * 16)   // 198656 B

// Persistent scratch (no allocations allowed)
__device__ float g_h0[2][BZ * HH];
__device__ float g_h1[2][BZ * HH];
__device__ int          g_count;
__device__ volatile int g_epoch;

// ---------------------------------------------------------------------------
__global__ void prep_kernel() {
    int i = blockIdx.x * blockDim.x + threadIdx.x;
    int stride = gridDim.x * blockDim.x;
    float* a = &g_h0[0][0];
    float* b = &g_h1[0][0];
    for (int k = i; k < 2 * BZ * HH; k += stride) { a[k] = 0.f; b[k] = 0.f; }
    if (i == 0) { g_count = 0; g_epoch = 0; }
}

// ---------------------------------------------------------------------------
__device__ __forceinline__ unsigned long long pack2(float x, float y) {
    unsigned long long r;
    asm("mov.b64 %0, {%1, %2};" : "=l"(r) : "f"(x), "f"(y));
    return r;
}
__device__ __forceinline__ float2 unpack2(unsigned long long v) {
    float2 r;
    asm("mov.b64 {%0, %1}, %2;" : "=f"(r.x), "=f"(r.y) : "l"(v));
    return r;
}
__device__ __forceinline__ void fma2(unsigned long long& d,
                                     unsigned long long a,
                                     unsigned long long b) {
    asm("fma.rn.f32x2 %0, %1, %2, %0;" : "+l"(d) : "l"(a), "l"(b));
}
__device__ __forceinline__ void cp16(uint32_t dst_smem, const void* src) {
    asm volatile("cp.async.cg.shared.global [%0], [%1], 16;" :: "r"(dst_smem), "l"(src));
}
__device__ __forceinline__ void cp_commit() {
    asm volatile("cp.async.commit_group;");
}
template <int N>
__device__ __forceinline__ void cp_wait() {
    asm volatile("cp.async.wait_group %0;" :: "n"(N));
}

// Copy one 64b x 128k chunk (2048 float4) global -> A smem buffer.
__device__ __forceinline__ void load_chunk(float4* dst, const float* sp,
                                           long bstride, int koff, int tid) {
#pragma unroll
    for (int i = 0; i < 16; i++) {
        int idx = i * 128 + tid;          // 0..2047
        int b   = idx >> 5;
        int kq  = idx & 31;
        const float* g = sp + (long)b * bstride + koff + kq * 4;
        uint32_t d = (uint32_t)__cvta_generic_to_shared(dst + b * KP4 + kq);
        cp16(d, g);
    }
    cp_commit();
}

// ---------------------------------------------------------------------------
__global__ void __launch_bounds__(THREADS, 1)
rnn_persistent_kernel(const float* __restrict__ x,
                      const float* __restrict__ W0,
                      const float* __restrict__ b0,
                      const float* __restrict__ W1,
                      const float* __restrict__ b1,
                      float* __restrict__ out) {
    extern __shared__ float4 smem4[];
    float4* Ws4 = smem4;                 // [2048][4] float4  (W[k][16 cols])
    float4* As4 = smem4 + W_F4;          // 2 buffers of A_F4

    const int tid   = threadIdx.x;
    const int cta   = blockIdx.x;
    const int layer = cta >> 6;
    const int jcta  = (cta & 63) * NCOL;

    const float* W    = layer ? W1 : W0;
    const float* bias = layer ? b1 : b0;

    // One-time: weights into SMEM (k-major, 16 cols per CTA)
    for (int n = tid; n < W_F4; n += THREADS) {
        int k = n >> 2, q = n & 3;
        Ws4[n] = *reinterpret_cast<const float4*>(W + (long)k * 1024 + jcta + q * 4);
    }

    const int bg  = tid & 31;            // batch group: b0i=bg, b1i=bg+32
    const int jg  = tid >> 5;            // 0..3 -> cols jcta + 4*jg ..
    const int b0i = bg, b1i = bg + 32;
    const int jcol = jcta + jg * 4;

    const float4 bv = *reinterpret_cast<const float4*>(bias + jcol);
    const unsigned long long* W2 = reinterpret_cast<const unsigned long long*>(Ws4);
    const size_t FSOFF = (size_t)BZ * TT * HH;

    __syncthreads();

    for (int p = 0; p <= TT; p++) {
        const bool active = layer ? (p >= 1) : (p < TT);
        if (active) {
            const int t = layer ? (p - 1) : p;
            // half0 source: own-layer previous hidden
            const float* sp0 = layer ? g_h1[p & 1] : g_h0[(p + 1) & 1];
            // half1 source: x[t] (layer0) or h0[t] (layer1)
            const float* sp1 = layer ? g_h0[(p + 1) & 1] : (x + (long)t * DD);
            const long   bs1 = layer ? (long)HH : (long)TT * DD;

            unsigned long long c00 = 0ull, c01 = 0ull, c10 = 0ull, c11 = 0ull;

            // prime chunk 0
            load_chunk(As4, sp0, HH, 0, tid);

            for (int c = 0; c < NCHUNK; c++) {
                // prefetch next chunk into other buffer
                if (c + 1 < NCHUNK) {
                    int k0n = (c + 1) * CHUNK;
                    if (k0n < 1024)
                        load_chunk(As4 + ((c + 1) & 1) * A_F4, sp0, HH, k0n, tid);
                    else
                        load_chunk(As4 + ((c + 1) & 1) * A_F4, sp1, bs1, k0n - 1024, tid);
                    cp_wait<1>();
                } else {
                    cp_wait<0>();
                }
                __syncthreads();

                const float4* Ab = As4 + (c & 1) * A_F4;
                const int kbase = c * CHUNK;
#pragma unroll 4
                for (int kq = 0; kq < 32; kq++) {
                    float4 a0 = Ab[b0i * KP4 + kq];
                    float4 a1 = Ab[b1i * KP4 + kq];
                    int k = kbase + kq * 4;
#pragma unroll
                    for (int u = 0; u < 4; u++) {
                        unsigned long long wlo = W2[((long)(k + u) * 4 + jg) * 2 + 0];
                        unsigned long long whi = W2[((long)(k + u) * 4 + jg) * 2 + 1];
                        float av0 = (&a0.x)[u];
                        float av1 = (&a1.x)[u];
                        unsigned long long d0 = pack2(av0, av0);
                        unsigned long long d1 = pack2(av1, av1);
                        fma2(c00, d0, wlo);
                        fma2(c01, d0, whi);
                        fma2(c10, d1, wlo);
                        fma2(c11, d1, whi);
                    }
                }
                __syncthreads();
            }

            // epilogue: bias + tanh + stores
            float2 r00 = unpack2(c00), r01 = unpack2(c01);
            float2 r10 = unpack2(c10), r11 = unpack2(c11);
            float4 o0, o1;
            o0.x = tanhf(r00.x + bv.x); o0.y = tanhf(r00.y + bv.y);
            o0.z = tanhf(r01.x + bv.z); o0.w = tanhf(r01.y + bv.w);
            o1.x = tanhf(r10.x + bv.x); o1.y = tanhf(r10.y + bv.y);
            o1.z = tanhf(r11.x + bv.z); o1.w = tanhf(r11.y + bv.w);

            if (layer == 0) {
                float* hw = g_h0[p & 1];
                __stcg(reinterpret_cast<float4*>(hw + b0i * HH + jcol), o0);
                __stcg(reinterpret_cast<float4*>(hw + b1i * HH + jcol), o1);
                if (p == TT - 1) {
                    *reinterpret_cast<float4*>(out + FSOFF + (size_t)b0i * 2048 + jcol) = o0;
                    *reinterpret_cast<float4*>(out + FSOFF + (size_t)b1i * 2048 + jcol) = o1;
                }
            } else {
                float* hw = g_h1[(p + 1) & 1];
                __stcg(reinterpret_cast<float4*>(hw + b0i * HH + jcol), o0);
                __stcg(reinterpret_cast<float4*>(hw + b1i * HH + jcol), o1);
                *reinterpret_cast<float4*>(out + (size_t)b0i * TT * HH + (size_t)t * HH + jcol) = o0;
                *reinterpret_cast<float4*>(out + (size_t)b1i * TT * HH + (size_t)t * HH + jcol) = o1;
                if (t == TT - 1) {
                    *reinterpret_cast<float4*>(out + FSOFF + (size_t)b0i * 2048 + 1024 + jcol) = o0;
                    *reinterpret_cast<float4*>(out + FSOFF + (size_t)b1i * 2048 + 1024 + jcol) = o1;
                }
            }
        }

        // ---- grid barrier (epoch-based) ----
        __threadfence();
        __syncthreads();
        if (tid == 0) {
            int e = g_epoch;
            int old = atomicAdd(&g_count, 1);
            if (((old + 1) & (NCTA - 1)) == 0) {
                __threadfence();
                atomicAdd((int*)&g_epoch, 1);
            } else {
                while (g_epoch == e) { __nanosleep(64); }
            }
        }
        __syncthreads();
    }
}

// ---------------------------------------------------------------------------
extern "C" void kernel_launch(void* const* d_in, const int* in_sizes, int n_in,
                              void* d_out, int out_size) {
    const float* x  = (const float*)d_in[0];
    const float* W0 = (const float*)d_in[1];
    const float* b0 = (const float*)d_in[2];
    const float* W1 = (const float*)d_in[3];
    const float* b1 = (const float*)d_in[4];
    float* out = (float*)d_out;

    cudaFuncSetAttribute(rnn_persistent_kernel,
                         cudaFuncAttributeMaxDynamicSharedMemorySize, SMEM_BYTES);

    prep_kernel<<<64, 256>>>();
    rnn_persistent_kernel<<<NCTA, THREADS, SMEM_BYTES>>>(x, W0, b0, W1, b1, out);
}